// round 16
// baseline (speedup 1.0000x reference)
#include <cuda_runtime.h>
#include <cuda_bf16.h>
#include <cstdint>
#include <cstddef>
typedef unsigned long long ull;
#define C3 384

__device__ float g_xw[(size_t)1024 * 256 * C3];     // [t][b][384] gate pre-acts
__device__ float g_seq1[(size_t)1024 * 256 * 128];  // [t][b][128] layer-1 outputs

// ---------------- scalar helpers ----------------
__device__ __forceinline__ ull ffma2(ull a, ull b, ull c) {
    ull d; asm("fma.rn.f32x2 %0,%1,%2,%3;" : "=l"(d) : "l"(a), "l"(b), "l"(c)); return d;
}
__device__ __forceinline__ ull pack2(float x, float y) {
    ull d; asm("mov.b64 %0,{%1,%2};" : "=l"(d) : "f"(x), "f"(y)); return d;
}
__device__ __forceinline__ float2 up2(ull v) {
    float x, y; asm("mov.b64 {%0,%1},%2;" : "=f"(x), "=f"(y) : "l"(v)); return make_float2(x, y);
}
__device__ __forceinline__ float sigm(float x) {   // sigmoid via HW tanh
    float t; asm("tanh.approx.f32 %0, %1;" : "=f"(t) : "f"(0.5f * x));
    return fmaf(0.5f, t, 0.5f);
}
__device__ __forceinline__ void pfL2(const void* p) {
    asm volatile("prefetch.global.L2 [%0];" :: "l"(p));
}
// packed bf16 pair: lo-half = bf16(e), hi-half = bf16(o)
__device__ __forceinline__ uint32_t bfpair_hi(float e, float o) {
    uint32_t d; asm("cvt.rn.bf16x2.f32 %0, %1, %2;" : "=r"(d) : "f"(o), "f"(e)); return d;
}
__device__ __forceinline__ uint32_t bfpair_lo(float e, float o, uint32_t hp) {
    float he = __uint_as_float(hp << 16);
    float ho = __uint_as_float(hp & 0xFFFF0000u);
    uint32_t d; asm("cvt.rn.bf16x2.f32 %0, %1, %2;" : "=r"(d) : "f"(o - ho), "f"(e - he)); return d;
}
__device__ __forceinline__ void mma16816(float* c, const uint32_t* a, const uint32_t* b) {
    asm volatile(
        "mma.sync.aligned.m16n8k16.row.col.f32.bf16.bf16.f32 "
        "{%0,%1,%2,%3}, {%4,%5,%6,%7}, {%8,%9}, {%0,%1,%2,%3};"
        : "+f"(c[0]), "+f"(c[1]), "+f"(c[2]), "+f"(c[3])
        : "r"(a[0]), "r"(a[1]), "r"(a[2]), "r"(a[3]), "r"(b[0]), "r"(b[1]));
}

// ============================================================
// k_xw_mma (frozen, R15): out[orow][c] = sum_k in[row][k]*W[k][c] + bias[c]
// via mma.sync m16n8k16 bf16-split-2 (3 terms, fp32 accum).
// ============================================================
template<int K, bool L1>
__global__ void __launch_bounds__(384, 1)
k_xw_mma(const float* __restrict__ in, const float* __restrict__ W,
         const float* __restrict__ bias) {
    constexpr int S = K / 16;
    constexpr int NB = S * 1536;
    constexpr int NA = S * 512;
    extern __shared__ __align__(16) uint32_t smw[];
    uint32_t* Bh = smw;
    uint32_t* Bl = Bh + NB;
    uint32_t* Af = Bl + NB;

    int tid = threadIdx.x, lane = tid & 31, w = tid >> 5;
    int g = lane >> 2, tg = lane & 3;
    int warp_m = w / 6, warp_n = w % 6;
    int bid = blockIdx.x;
    int nhalf = bid >= 74 ? 1 : 0;
    int n0 = nhalf * 192;
    const float* base = L1 ? in : (const float*)g_seq1;

    for (int i = tid; i < S * 768; i += 384) {
        int t = i & 31, nt = (i >> 5) % 24, s = i / 768;
        int gg = t >> 2, tt = t & 3;
        int col = n0 + nt * 8 + gg;
        int k = s * 16 + 2 * tt;
        float w00 = W[(size_t)k * C3 + col],       w01 = W[(size_t)(k + 1) * C3 + col];
        float w10 = W[(size_t)(k + 8) * C3 + col], w11 = W[(size_t)(k + 9) * C3 + col];
        uint32_t h0 = bfpair_hi(w00, w01), h1 = bfpair_hi(w10, w11);
        int idx = ((s * 24 + nt) * 32 + t) * 2;
        *(uint2*)&Bh[idx] = make_uint2(h0, h1);
        *(uint2*)&Bl[idx] = make_uint2(bfpair_lo(w00, w01, h0), bfpair_lo(w10, w11, h1));
    }

    float2 bv[4];
#pragma unroll
    for (int ntl = 0; ntl < 4; ntl++)
        bv[ntl] = *(const float2*)&bias[n0 + warp_n * 32 + ntl * 8 + 2 * tg];

    auto stageA = [&](int rt, uint32_t* A) {
        for (int i = tid; i < S * 128; i += 384) {
            int t = i & 31, mt = (i >> 5) & 3, s = i >> 7;
            int gg = t >> 2, tt = t & 3;
            int row0 = rt * 64 + mt * 16 + gg;
            const float* rp0 = base + (size_t)row0 * K + s * 16 + 2 * tt;
            const float* rp1 = rp0 + 8 * K;
            float2 v00 = *(const float2*)rp0;
            float2 v10 = *(const float2*)rp1;
            float2 v01 = *(const float2*)(rp0 + 8);
            float2 v11 = *(const float2*)(rp1 + 8);
            uint32_t h0 = bfpair_hi(v00.x, v00.y), h1 = bfpair_hi(v10.x, v10.y);
            uint32_t h2 = bfpair_hi(v01.x, v01.y), h3 = bfpair_hi(v11.x, v11.y);
            int idx = ((s * 4 + mt) * 32 + t) * 4;
            *(uint4*)&A[idx] = make_uint4(h0, h1, h2, h3);
            *(uint4*)&A[NA + idx] = make_uint4(
                bfpair_lo(v00.x, v00.y, h0), bfpair_lo(v10.x, v10.y, h1),
                bfpair_lo(v01.x, v01.y, h2), bfpair_lo(v11.x, v11.y, h3));
        }
    };

    int rt = nhalf ? bid - 74 : bid;
    stageA(rt, Af);
    __syncthreads();
    int buf = 0;

    for (; rt < 4096; rt += 74) {
        const uint32_t* Ab = Af + buf * 2 * NA;
        float acc[2][4][4];
#pragma unroll
        for (int m = 0; m < 2; m++)
#pragma unroll
            for (int n = 0; n < 4; n++)
#pragma unroll
                for (int q = 0; q < 4; q++) acc[m][n][q] = 0.f;

#pragma unroll
        for (int term = 0; term < 3; term++) {
            const uint32_t* A = Ab + (term == 1 ? NA : 0);
            const uint32_t* B = (term == 2) ? Bl : Bh;
#pragma unroll
            for (int s = 0; s < S; s++) {
                uint4 af[2];
#pragma unroll
                for (int m = 0; m < 2; m++)
                    af[m] = *(const uint4*)&A[((s * 4 + warp_m * 2 + m) * 32 + lane) * 4];
                uint2 bf[4];
#pragma unroll
                for (int n = 0; n < 4; n++)
                    bf[n] = *(const uint2*)&B[((s * 24 + warp_n * 4 + n) * 32 + lane) * 2];
#pragma unroll
                for (int m = 0; m < 2; m++)
#pragma unroll
                    for (int n = 0; n < 4; n++)
                        mma16816(acc[m][n], (const uint32_t*)&af[m], (const uint32_t*)&bf[n]);
            }
        }

        int nrt = rt + 74;
        if (nrt < 4096) stageA(nrt, Af + (buf ^ 1) * 2 * NA);

#pragma unroll
        for (int m = 0; m < 2; m++) {
            int rin = rt * 64 + warp_m * 32 + m * 16 + g;
            int r2 = rin + 8;
            int o1 = L1 ? ((rin & 1023) * 256 + (rin >> 10)) : rin;
            int o2 = L1 ? ((r2 & 1023) * 256 + (r2 >> 10)) : r2;
#pragma unroll
            for (int n = 0; n < 4; n++) {
                int co = n0 + warp_n * 32 + n * 8 + 2 * tg;
                *(float2*)&g_xw[(size_t)o1 * C3 + co] =
                    make_float2(acc[m][n][0] + bv[n].x, acc[m][n][1] + bv[n].y);
                *(float2*)&g_xw[(size_t)o2 * C3 + co] =
                    make_float2(acc[m][n][2] + bv[n].x, acc[m][n][3] + bv[n].y);
            }
        }
        __syncthreads();
        buf ^= 1;
    }
}

// ============================================================
// k_gru v7: 768 threads (24 warps), weights in SMEM.
// Thread = (column c, batch b); 1 dot of length 128 per thread.
// Wq[32][384] ulonglong2: one LDS.128 -> weights for h quad (4 k's).
// ============================================================
template<bool WSEQ>
__global__ void __launch_bounds__(768, 1) k_gru(const float* __restrict__ Uw,
                                                const float* __restrict__ br,
                                                float* __restrict__ stateOut,
                                                float* __restrict__ xOut) {
    extern __shared__ __align__(16) char gsm[];
    ulonglong2* Wq = (ulonglong2*)gsm;              // [32][384]
    float* hs = (float*)(gsm + 32 * 384 * 16);      // [2][128]
    float* rs = hs + 256;                           // [2][384]
    int tid = threadIdx.x, p = blockIdx.x;
    int c = tid % 384, b = tid / 384;

    // stage packed weights: Wq[j][c] = {(U[4j][c],U[4j+1][c]), (U[4j+2][c],U[4j+3][c])}
    for (int i = tid; i < 32 * 384; i += 768) {
        int j = i / 384, cc = i % 384;
        Wq[i] = make_ulonglong2(
            pack2(Uw[(size_t)(4 * j) * C3 + cc],     Uw[(size_t)(4 * j + 1) * C3 + cc]),
            pack2(Uw[(size_t)(4 * j + 2) * C3 + cc], Uw[(size_t)(4 * j + 3) * C3 + cc]));
    }
    float brc = br[c];
    if (tid < 256) hs[tid] = 0.f;
    int u = tid & 127, bl = (tid >> 7) & 1;
    bool g = tid < 256;
    int bb = 2 * p + bl;
    const float* xq = g_xw + (size_t)bb * C3 + u;
    float* sq = g_seq1 + (size_t)bb * 128 + u;
    bool pf = g && ((u & 31) == 0);
    float hval = 0.f;
    __syncthreads();

    for (int t = 0; t < 1024; t++) {
        float xz = 0.f, xr = 0.f, xh = 0.f;
        if (g) {
            const float* q = xq + (size_t)t * (256 * C3);
            xz = q[0]; xr = q[128]; xh = q[256];
        }
        if (pf && t < 1023) {
            const float* q = xq + (size_t)(t + 1) * (256 * C3);
            pfL2(q); pfL2(q + 128); pfL2(q + 256);
        }
        ull a0 = 0ull, a1 = 0ull;   // 2 chains
        const float* hb = hs + b * 128;
#pragma unroll
        for (int i = 0; i < 32; i++) {
            ulonglong2 q = *(const ulonglong2*)&hb[4 * i];   // broadcast (warp-uniform b)
            ulonglong2 w = Wq[i * 384 + c];                  // 16B lane stride: conflict-free
            a0 = ffma2(q.x, w.x, a0);
            a1 = ffma2(q.y, w.y, a1);
        }
        float2 v0 = up2(a0), v1 = up2(a1);
        rs[b * 384 + c] = (v0.x + v0.y) + (v1.x + v1.y) + brc;
        __syncthreads();
        if (g) {
            const float* rr = rs + bl * 384;
            float z  = sigm(xz + rr[u]);
            float r  = sigm(xr + rr[u + 128]);
            float hh = fmaxf(xh + r * rr[u + 256], 0.f);
            float hn = z * hval + (1.f - z) * hh;
            hval = hn;
            hs[bl * 128 + u] = hn;
            if (WSEQ) sq[(size_t)t * (256 * 128)] = hn;
            if (t == 1023) {
                stateOut[(size_t)bb * 128 + u] = hn;
                if (xOut) xOut[(size_t)bb * 128 + u] = hn;
            }
        }
        __syncthreads();
    }
}

extern "C" void kernel_launch(void* const* d_in, const int* in_sizes, int n_in,
                              void* d_out, int out_size) {
    const float* x  = (const float*)d_in[0];
    const float* W1 = (const float*)d_in[1];
    const float* U1 = (const float*)d_in[2];
    const float* b1 = (const float*)d_in[3];
    const float* W2 = (const float*)d_in[4];
    const float* U2 = (const float*)d_in[5];
    const float* b2 = (const float*)d_in[6];
    float* out = (float*)d_out;  // [x | state1 | state2], each 256*128

    int sm1 = 20480 * (64 / 16);     // 81920
    int sm2 = 20480 * (128 / 16);    // 163840
    int smg = 32 * 384 * 16 + (256 + 768) * 4;   // 200704
    cudaFuncSetAttribute(k_xw_mma<64, true>,   cudaFuncAttributeMaxDynamicSharedMemorySize, sm1);
    cudaFuncSetAttribute(k_xw_mma<128, false>, cudaFuncAttributeMaxDynamicSharedMemorySize, sm2);
    cudaFuncSetAttribute(k_gru<true>,  cudaFuncAttributeMaxDynamicSharedMemorySize, smg);
    cudaFuncSetAttribute(k_gru<false>, cudaFuncAttributeMaxDynamicSharedMemorySize, smg);

    k_xw_mma<64, true><<<148, 384, sm1>>>(x, W1, b1);
    k_gru<true><<<128, 768, smg>>>(U1, b1 + C3, out + 32768, nullptr);
    k_xw_mma<128, false><<<148, 384, sm2>>>(nullptr, W2, b2);
    k_gru<false><<<128, 768, smg>>>(U2, b2 + C3, out + 65536, out);
}

// round 17
// speedup vs baseline: 2.0112x; 2.0112x over previous
#include <cuda_runtime.h>
#include <cuda_bf16.h>
#include <cstdint>
#include <cstddef>
typedef unsigned long long ull;
#define C3 384

__device__ float g_xw[(size_t)1024 * 256 * C3];     // [t][b][384] gate pre-acts
__device__ float g_seq1[(size_t)1024 * 256 * 128];  // [t][b][128] layer-1 outputs

// ---------------- scalar helpers ----------------
__device__ __forceinline__ ull ffma2(ull a, ull b, ull c) {
    ull d; asm("fma.rn.f32x2 %0,%1,%2,%3;" : "=l"(d) : "l"(a), "l"(b), "l"(c)); return d;
}
__device__ __forceinline__ ull pack2(float x, float y) {
    ull d; asm("mov.b64 %0,{%1,%2};" : "=l"(d) : "f"(x), "f"(y)); return d;
}
__device__ __forceinline__ float2 up2(ull v) {
    float x, y; asm("mov.b64 {%0,%1},%2;" : "=f"(x), "=f"(y) : "l"(v)); return make_float2(x, y);
}
__device__ __forceinline__ float sigm(float x) {   // sigmoid via HW tanh
    float t; asm("tanh.approx.f32 %0, %1;" : "=f"(t) : "f"(0.5f * x));
    return fmaf(0.5f, t, 0.5f);
}
__device__ __forceinline__ void pfL2(const void* p) {
    asm volatile("prefetch.global.L2 [%0];" :: "l"(p));
}
// packed bf16 pair: lo-half = bf16(e), hi-half = bf16(o)
__device__ __forceinline__ uint32_t bfpair_hi(float e, float o) {
    uint32_t d; asm("cvt.rn.bf16x2.f32 %0, %1, %2;" : "=r"(d) : "f"(o), "f"(e)); return d;
}
__device__ __forceinline__ uint32_t bfpair_lo(float e, float o, uint32_t hp) {
    float he = __uint_as_float(hp << 16);
    float ho = __uint_as_float(hp & 0xFFFF0000u);
    uint32_t d; asm("cvt.rn.bf16x2.f32 %0, %1, %2;" : "=r"(d) : "f"(o - ho), "f"(e - he)); return d;
}
__device__ __forceinline__ void mma16816(float* c, const uint32_t* a, const uint32_t* b) {
    asm volatile(
        "mma.sync.aligned.m16n8k16.row.col.f32.bf16.bf16.f32 "
        "{%0,%1,%2,%3}, {%4,%5,%6,%7}, {%8,%9}, {%0,%1,%2,%3};"
        : "+f"(c[0]), "+f"(c[1]), "+f"(c[2]), "+f"(c[3])
        : "r"(a[0]), "r"(a[1]), "r"(a[2]), "r"(a[3]), "r"(b[0]), "r"(b[1]));
}

// ============================================================
// k_xw_mma v2: mma.sync m16n8k16 bf16-split-2 (3 terms, fp32 accum),
// with REGISTER-PIPELINED A staging: tile t+1's LDGs issue before the
// MMA section (latency hidden), cvt+STS happen after.
// 148 persistent CTAs, 74 per N-half (192 cols). CTA tile 64 x 192.
// ============================================================
template<int K, bool L1>
__global__ void __launch_bounds__(384, 1)
k_xw_mma(const float* __restrict__ in, const float* __restrict__ W,
         const float* __restrict__ bias) {
    constexpr int S = K / 16;
    constexpr int NB = S * 1536;
    constexpr int NA = S * 512;
    constexpr int NIT = (S * 128 + 383) / 384;
    extern __shared__ __align__(16) uint32_t smw[];
    uint32_t* Bh = smw;
    uint32_t* Bl = Bh + NB;
    uint32_t* Af = Bl + NB;

    int tid = threadIdx.x, lane = tid & 31, w = tid >> 5;
    int g = lane >> 2, tg = lane & 3;
    int warp_m = w / 6, warp_n = w % 6;
    int bid = blockIdx.x;
    int nhalf = bid >= 74 ? 1 : 0;
    int n0 = nhalf * 192;
    const float* base = L1 ? in : (const float*)g_seq1;

    for (int i = tid; i < S * 768; i += 384) {
        int t = i & 31, nt = (i >> 5) % 24, s = i / 768;
        int gg = t >> 2, tt = t & 3;
        int col = n0 + nt * 8 + gg;
        int k = s * 16 + 2 * tt;
        float w00 = W[(size_t)k * C3 + col],       w01 = W[(size_t)(k + 1) * C3 + col];
        float w10 = W[(size_t)(k + 8) * C3 + col], w11 = W[(size_t)(k + 9) * C3 + col];
        uint32_t h0 = bfpair_hi(w00, w01), h1 = bfpair_hi(w10, w11);
        int idx = ((s * 24 + nt) * 32 + t) * 2;
        *(uint2*)&Bh[idx] = make_uint2(h0, h1);
        *(uint2*)&Bl[idx] = make_uint2(bfpair_lo(w00, w01, h0), bfpair_lo(w10, w11, h1));
    }

    float2 bv[4];
#pragma unroll
    for (int ntl = 0; ntl < 4; ntl++)
        bv[ntl] = *(const float2*)&bias[n0 + warp_n * 32 + ntl * 8 + 2 * tg];

    float2 v[NIT][4];   // register-staged A values for the NEXT tile
    auto loadA = [&](int rt) {
#pragma unroll
        for (int i = 0; i < NIT; i++) {
            int idx = tid + i * 384;
            if (idx < S * 128) {
                int t = idx & 31, mt = (idx >> 5) & 3, s = idx >> 7;
                int gg = t >> 2, tt = t & 3;
                const float* rp0 = base + (size_t)(rt * 64 + mt * 16 + gg) * K + s * 16 + 2 * tt;
                v[i][0] = *(const float2*)rp0;
                v[i][1] = *(const float2*)(rp0 + 8 * K);
                v[i][2] = *(const float2*)(rp0 + 8);
                v[i][3] = *(const float2*)(rp0 + 8 * K + 8);
            }
        }
    };
    auto storeA = [&](uint32_t* A) {
#pragma unroll
        for (int i = 0; i < NIT; i++) {
            int idx = tid + i * 384;
            if (idx < S * 128) {
                uint32_t h0 = bfpair_hi(v[i][0].x, v[i][0].y);
                uint32_t h1 = bfpair_hi(v[i][1].x, v[i][1].y);
                uint32_t h2 = bfpair_hi(v[i][2].x, v[i][2].y);
                uint32_t h3 = bfpair_hi(v[i][3].x, v[i][3].y);
                int o = idx * 4;
                *(uint4*)&A[o] = make_uint4(h0, h1, h2, h3);
                *(uint4*)&A[NA + o] = make_uint4(
                    bfpair_lo(v[i][0].x, v[i][0].y, h0), bfpair_lo(v[i][1].x, v[i][1].y, h1),
                    bfpair_lo(v[i][2].x, v[i][2].y, h2), bfpair_lo(v[i][3].x, v[i][3].y, h3));
            }
        }
    };

    int rt = nhalf ? bid - 74 : bid;
    loadA(rt);
    storeA(Af);
    __syncthreads();
    int buf = 0;

    for (; rt < 4096; rt += 74) {
        int nrt = rt + 74;
        if (nrt < 4096) loadA(nrt);          // LDGs in flight; hidden under MMA

        const uint32_t* Ab = Af + buf * 2 * NA;
        float acc[2][4][4];
#pragma unroll
        for (int m = 0; m < 2; m++)
#pragma unroll
            for (int n = 0; n < 4; n++)
#pragma unroll
                for (int q = 0; q < 4; q++) acc[m][n][q] = 0.f;

#pragma unroll
        for (int term = 0; term < 3; term++) {
            const uint32_t* A = Ab + (term == 1 ? NA : 0);
            const uint32_t* B = (term == 2) ? Bl : Bh;
#pragma unroll
            for (int s = 0; s < S; s++) {
                uint4 af[2];
#pragma unroll
                for (int m = 0; m < 2; m++)
                    af[m] = *(const uint4*)&A[((s * 4 + warp_m * 2 + m) * 32 + lane) * 4];
                uint2 bf[4];
#pragma unroll
                for (int n = 0; n < 4; n++)
                    bf[n] = *(const uint2*)&B[((s * 24 + warp_n * 4 + n) * 32 + lane) * 2];
#pragma unroll
                for (int m = 0; m < 2; m++)
#pragma unroll
                    for (int n = 0; n < 4; n++)
                        mma16816(acc[m][n], (const uint32_t*)&af[m], (const uint32_t*)&bf[n]);
            }
        }

        // epilogue: acc -> g_xw with bias and (L1) transpose
#pragma unroll
        for (int m = 0; m < 2; m++) {
            int rin = rt * 64 + warp_m * 32 + m * 16 + g;
            int r2 = rin + 8;
            int o1 = L1 ? ((rin & 1023) * 256 + (rin >> 10)) : rin;
            int o2 = L1 ? ((r2 & 1023) * 256 + (r2 >> 10)) : r2;
#pragma unroll
            for (int n = 0; n < 4; n++) {
                int co = n0 + warp_n * 32 + n * 8 + 2 * tg;
                *(float2*)&g_xw[(size_t)o1 * C3 + co] =
                    make_float2(acc[m][n][0] + bv[n].x, acc[m][n][1] + bv[n].y);
                *(float2*)&g_xw[(size_t)o2 * C3 + co] =
                    make_float2(acc[m][n][2] + bv[n].x, acc[m][n][3] + bv[n].y);
            }
        }

        if (nrt < 4096) storeA(Af + (buf ^ 1) * 2 * NA);   // cvt + STS only
        __syncthreads();
        buf ^= 1;
    }
}

// ============================================================
// k_gru (FROZEN — R13 optimum): 1 CTA = 2 batch rows; 384 threads = cols.
// Interleaved h; recurrent weights register-resident (64 packed k-pairs).
// ============================================================
template<bool WSEQ>
__global__ void __launch_bounds__(384, 1) k_gru(const float* __restrict__ Uw,
                                                const float* __restrict__ br,
                                                float* __restrict__ stateOut,
                                                float* __restrict__ xOut) {
    __shared__ __align__(16) float hsi[256];
    __shared__ __align__(8) float2 rss[C3];
    int c = threadIdx.x, p = blockIdx.x;
    ull wp[64];
#pragma unroll
    for (int j = 0; j < 64; j++)
        wp[j] = pack2(Uw[(size_t)(2 * j) * C3 + c], Uw[(size_t)(2 * j + 1) * C3 + c]);
    float brc = br[c];
    if (c < 256) hsi[c] = 0.f;
    int u = c & 127, bl = (c >> 7) & 1;
    bool g = c < 256;
    int b = 2 * p + bl;
    int hidx = 4 * (u >> 1) + 2 * bl + (u & 1);
    const float* xq = g_xw + (size_t)b * C3 + u;
    float* sq = g_seq1 + (size_t)b * 128 + u;
    bool pf = g && ((u & 31) == 0);
    float hval = 0.f;
    __syncthreads();
    for (int t = 0; t < 1024; t++) {
        float xz = 0.f, xr = 0.f, xh = 0.f;
        if (g) {
            const float* q = xq + (size_t)t * (256 * C3);
            xz = q[0]; xr = q[128]; xh = q[256];
        }
        if (pf && t < 1023) {
            const float* q = xq + (size_t)(t + 1) * (256 * C3);
            pfL2(q); pfL2(q + 128); pfL2(q + 256);
        }
        ull a0 = 0ull, a1 = 0ull;
#pragma unroll
        for (int j = 0; j < 64; j++) {
            ulonglong2 q = *(const ulonglong2*)&hsi[4 * j];
            a0 = ffma2(q.x, wp[j], a0);
            a1 = ffma2(q.y, wp[j], a1);
        }
        float2 v0 = up2(a0), v1 = up2(a1);
        rss[c] = make_float2(v0.x + v0.y + brc, v1.x + v1.y + brc);
        __syncthreads();
        if (g) {
            float2 rz = rss[u], rr2 = rss[u + 128], rh = rss[u + 256];
            float z  = sigm(xz + (bl ? rz.y : rz.x));
            float r  = sigm(xr + (bl ? rr2.y : rr2.x));
            float hh = fmaxf(xh + r * (bl ? rh.y : rh.x), 0.f);
            float hn = z * hval + (1.f - z) * hh;
            hval = hn;
            hsi[hidx] = hn;
            if (WSEQ) sq[(size_t)t * (256 * 128)] = hn;
            if (t == 1023) {
                stateOut[(size_t)b * 128 + u] = hn;
                if (xOut) xOut[(size_t)b * 128 + u] = hn;
            }
        }
        __syncthreads();
    }
}

extern "C" void kernel_launch(void* const* d_in, const int* in_sizes, int n_in,
                              void* d_out, int out_size) {
    const float* x  = (const float*)d_in[0];
    const float* W1 = (const float*)d_in[1];
    const float* U1 = (const float*)d_in[2];
    const float* b1 = (const float*)d_in[3];
    const float* W2 = (const float*)d_in[4];
    const float* U2 = (const float*)d_in[5];
    const float* b2 = (const float*)d_in[6];
    float* out = (float*)d_out;  // [x | state1 | state2], each 256*128

    int sm1 = 20480 * (64 / 16);     // 81920
    int sm2 = 20480 * (128 / 16);    // 163840
    cudaFuncSetAttribute(k_xw_mma<64, true>,   cudaFuncAttributeMaxDynamicSharedMemorySize, sm1);
    cudaFuncSetAttribute(k_xw_mma<128, false>, cudaFuncAttributeMaxDynamicSharedMemorySize, sm2);

    k_xw_mma<64, true><<<148, 384, sm1>>>(x, W1, b1);
    k_gru<true><<<128, 384>>>(U1, b1 + C3, out + 32768, nullptr);
    k_xw_mma<128, false><<<148, 384, sm2>>>(nullptr, W2, b2);
    k_gru<false><<<128, 384>>>(U2, b2 + C3, out + 65536, out);
}